// round 13
// baseline (speedup 1.0000x reference)
#include <cuda_runtime.h>
#include <cuda_bf16.h>
#include <cuda_fp16.h>
#include <cstdint>

// ---------------------------------------------------------------------------
// RSAGE_Hetero round 12: single persistent mega-kernel.
//  - 296 CTAs (2/SM, wave-1 resident), 5 stages with epoch global barriers
//  - dynamic per-stage work queues (atomic pop, reset at kernel end)
//  - graph CTAs (144) build CSR, then join the GEMM queue
//  - weights split/combined on the fly; K1 eliminated
//  - GEMM = R9 proven config (BM=64, 256 threads, no reg pipeline)
// ---------------------------------------------------------------------------

constexpr int NPn  = 50000;
constexpr int NAn  = 20000;
constexpr int DH   = 128;
constexpr int DOUT = 64;
constexpr int EWn  = 250000;
constexpr int ECn  = 500000;
constexpr int ERn  = 250000;
constexpr int NT   = 2 * NPn + NAn;      // 120000
constexpr int ET   = EWn + ECn + ERn;    // 1,000,000
constexpr int NCTA = 296;                // 2 CTAs/SM on 148 SMs
constexpr int GC   = 144;                // graph CTAs

constexpr int gNP = (NPn + 63) / 64;     // 782
constexpr int gNA = (NAn + 63) / 64;     // 313

// stage-1 tile ranges (yah | yph | yrh | S1p | S1a)
constexpr int S1E0 = gNA, S1E1 = S1E0 + gNP, S1E2 = S1E1 + gNP,
              S1E3 = S1E2 + gNP, S1E4 = S1E3 + gNA;   // 2972
// stage-3 tile ranges (zah | zph | S2)
constexpr int S3E0 = gNA, S3E1 = S3E0 + gNP, S3E2 = S3E1 + gNP;  // 1877
constexpr int NG1 = (NPn + NAn + 63) / 64;   // 1094 units of 64 nodes
constexpr int NG2 = (NPn + 63) / 64;         // 782

constexpr int LDSC = 136;
constexpr int SMEM_MAIN = 2 * 64 * LDSC * 2 + 2 * 128 * LDSC * 2;  // 104448
constexpr int SMEM_TOT  = SMEM_MAIN + 16;

// ------------------------------ scratch ------------------------------------
__device__ __half g_yah[NAn * DH];
__device__ __half g_yph[NPn * DH];
__device__ __half g_yrh[NPn * DH];
__device__ __half g_zah[NAn * DOUT];
__device__ __half g_zph[NPn * DOUT];
__device__ float  g_S1p[NPn * DH];
__device__ float  g_S1a[NAn * DH];
__device__ float  g_S2 [NPn * DOUT];
__device__ __nv_bfloat16 g_hp1h[NPn * DH], g_hp1l[NPn * DH];
__device__ __nv_bfloat16 g_ha1h[NAn * DH], g_ha1l[NAn * DH];

__device__ int g_deg[NT], g_off[NT + 1], g_cur[NT], g_src[ET];
__device__ int g_bsum[GC], g_bbase[GC];
__device__ unsigned g_gb[12];    // monotonic epoch barrier counters
__device__ unsigned g_q[4];      // work queues (reset at kernel end)

// --------------------------- PTX helpers -----------------------------------
__device__ __forceinline__ uint32_t smem_u32(const void* p) {
    uint32_t a;
    asm("{ .reg .u64 t; cvta.to.shared.u64 t, %1; cvt.u32.u64 %0, t; }"
        : "=r"(a) : "l"(p));
    return a;
}

__device__ __forceinline__ void ldmx4(uint32_t* r, uint32_t addr) {
    asm volatile(
        "ldmatrix.sync.aligned.m8n8.x4.shared.b16 {%0,%1,%2,%3}, [%4];"
        : "=r"(r[0]), "=r"(r[1]), "=r"(r[2]), "=r"(r[3]) : "r"(addr));
}

__device__ __forceinline__ void mma16816(float* c, const uint32_t* a,
                                         uint32_t b0, uint32_t b1) {
    asm volatile(
        "mma.sync.aligned.m16n8k16.row.col.f32.bf16.bf16.f32 "
        "{%0,%1,%2,%3}, {%4,%5,%6,%7}, {%8,%9}, {%0,%1,%2,%3};"
        : "+f"(c[0]), "+f"(c[1]), "+f"(c[2]), "+f"(c[3])
        : "r"(a[0]), "r"(a[1]), "r"(a[2]), "r"(a[3]), "r"(b0), "r"(b1));
}

// epoch barrier: monotonic counter, replay-safe, no resets needed
__device__ __forceinline__ void gbar(int idx, int n) {
    __syncthreads();
    if (threadIdx.x == 0) {
        __threadfence();
        unsigned t = atomicAdd(&g_gb[idx], 1u);
        unsigned target = (t / (unsigned)n + 1u) * (unsigned)n;
        while (*(volatile unsigned*)&g_gb[idx] < target) __nanosleep(64);
    }
    __syncthreads();
    __threadfence();
}

// --------------------------- graph program (144 CTAs) -----------------------
__device__ void graph_program(int c, char* smemRaw,
                              const int* wsrc, const int* wdst,
                              const int* csrc, const int* cdst,
                              const int* rsrc, const int* rdst) {
    int* s = (int*)smemRaw;
    const int tid = threadIdx.x;
    const int tg = c * 256 + tid;
    const int stride = GC * 256;

    // phase Z: zero deg
    for (int i = tg; i < NT; i += stride) g_deg[i] = 0;
    gbar(4, GC);

    // phase A: histogram
    for (int i = tg; i < EWn / 4; i += stride) {
        int4 d = ((const int4*)wdst)[i];
        atomicAdd(&g_deg[d.x], 1); atomicAdd(&g_deg[d.y], 1);
        atomicAdd(&g_deg[d.z], 1); atomicAdd(&g_deg[d.w], 1);
    }
    for (int i = tg; i < ECn / 4; i += stride) {
        int4 d = ((const int4*)cdst)[i];
        atomicAdd(&g_deg[NPn + d.x], 1); atomicAdd(&g_deg[NPn + d.y], 1);
        atomicAdd(&g_deg[NPn + d.z], 1); atomicAdd(&g_deg[NPn + d.w], 1);
    }
    for (int i = tg; i < ERn / 4; i += stride) {
        int4 d = ((const int4*)rdst)[i];
        atomicAdd(&g_deg[2 * NPn + d.x], 1); atomicAdd(&g_deg[2 * NPn + d.y], 1);
        atomicAdd(&g_deg[2 * NPn + d.z], 1); atomicAdd(&g_deg[2 * NPn + d.w], 1);
    }
    gbar(5, GC);

    // phase B1: per-CTA chunk scan (1024 entries)
    const int i0 = c * 1024 + tid * 4;
    int e[4];
    int tsum = 0;
    #pragma unroll
    for (int k = 0; k < 4; k++) {
        e[k] = (i0 + k < NT) ? g_deg[i0 + k] : 0;
        tsum += e[k];
    }
    s[tid] = tsum;
    __syncthreads();
    #pragma unroll
    for (int d = 1; d < 256; d <<= 1) {
        int v = (tid >= d) ? s[tid - d] : 0;
        __syncthreads();
        s[tid] += v;
        __syncthreads();
    }
    const int pre = s[tid] - tsum;
    if (tid == 255) g_bsum[c] = s[255];
    gbar(6, GC);

    // phase B2: CTA 0 scans block sums
    if (c == 0) {
        int v = (tid < GC) ? g_bsum[tid] : 0;
        s[tid] = v;
        __syncthreads();
        #pragma unroll
        for (int d = 1; d < 256; d <<= 1) {
            int t = (tid >= d) ? s[tid - d] : 0;
            __syncthreads();
            s[tid] += t;
            __syncthreads();
        }
        if (tid < GC) g_bbase[tid] = s[tid] - v;
        if (tid == 0) g_off[NT] = ET;
    }
    gbar(7, GC);

    // phase B3: write offsets
    {
        int run = g_bbase[c] + pre;
        #pragma unroll
        for (int k = 0; k < 4; k++) {
            if (i0 + k < NT) {
                g_off[i0 + k] = run;
                g_cur[i0 + k] = run;
                run += e[k];
            }
        }
    }
    gbar(8, GC);

    // phase C: fill
    for (int i = tg; i < EWn / 4; i += stride) {
        int4 d = ((const int4*)wdst)[i];
        int4 sv = ((const int4*)wsrc)[i];
        g_src[atomicAdd(&g_cur[d.x], 1)] = sv.x;
        g_src[atomicAdd(&g_cur[d.y], 1)] = sv.y;
        g_src[atomicAdd(&g_cur[d.z], 1)] = sv.z;
        g_src[atomicAdd(&g_cur[d.w], 1)] = sv.w;
    }
    for (int i = tg; i < ECn / 4; i += stride) {
        int4 d = ((const int4*)cdst)[i];
        int4 sv = ((const int4*)csrc)[i];
        g_src[atomicAdd(&g_cur[NPn + d.x], 1)] = sv.x;
        g_src[atomicAdd(&g_cur[NPn + d.y], 1)] = sv.y;
        g_src[atomicAdd(&g_cur[NPn + d.z], 1)] = sv.z;
        g_src[atomicAdd(&g_cur[NPn + d.w], 1)] = sv.w;
    }
    for (int i = tg; i < ERn / 4; i += stride) {
        int4 d = ((const int4*)rdst)[i];
        int4 sv = ((const int4*)rsrc)[i];
        g_src[atomicAdd(&g_cur[2 * NPn + d.x], 1)] = sv.x;
        g_src[atomicAdd(&g_cur[2 * NPn + d.y], 1)] = sv.y;
        g_src[atomicAdd(&g_cur[2 * NPn + d.z], 1)] = sv.z;
        g_src[atomicAdd(&g_cur[2 * NPn + d.w], 1)] = sv.w;
    }
}

// ---------------------- GEMM tile (BM=64, 256 threads) -----------------------
// C[m0:m0+64, 0:BN] = A[.,128] @ (alpha*(W+W2))[BN,128]^T (+ bs*(b1+b2))
// 3-term split (Ahi*Whi + Alo*Whi + Ahi*Wlo), fp32 accum.
template <int BN>
__device__ void gemm_tile(char* smemRaw, int m0, int M,
                          const void* A, const void* Alo,
                          const float* W, const float* W2, float alpha,
                          void* C, int outHalf,
                          const float* b1, const float* b2, float bs) {
    constexpr int LDS = LDSC;
    constexpr int BM  = 64;
    constexpr int MT  = (BN == 128) ? 2 : 1;
    constexpr int MW  = (BN == 128) ? 2 : 4;

    __nv_bfloat16* sm  = (__nv_bfloat16*)smemRaw;
    __nv_bfloat16* sAhi = sm;
    __nv_bfloat16* sAlo = sAhi + BM * LDS;
    __nv_bfloat16* sWhi = sAlo + BM * LDS;
    __nv_bfloat16* sWlo = sWhi + BN * LDS;

    const int tid  = threadIdx.x;
    const int lane = tid & 31;
    const int wid  = tid >> 5;
    const int cg   = (tid & 15) * 8;

    // ---- A tile ----
    if (Alo) {
        const __nv_bfloat16* Ah = (const __nv_bfloat16*)A;
        const __nv_bfloat16* Al = (const __nv_bfloat16*)Alo;
        #pragma unroll
        for (int r = tid >> 4; r < BM; r += 16) {
            const int gm = m0 + r;
            uint4 vh = make_uint4(0, 0, 0, 0), vl = vh;
            if (gm < M) {
                vh = *(const uint4*)(Ah + (size_t)gm * 128 + cg);
                vl = *(const uint4*)(Al + (size_t)gm * 128 + cg);
            }
            *(uint4*)(sAhi + r * LDS + cg) = vh;
            *(uint4*)(sAlo + r * LDS + cg) = vl;
        }
    } else {
        const float* Af = (const float*)A;
        #pragma unroll
        for (int r = tid >> 4; r < BM; r += 16) {
            const int gm = m0 + r;
            float4 v0 = make_float4(0.f, 0.f, 0.f, 0.f), v1 = v0;
            if (gm < M) {
                const float4* p = (const float4*)(Af + (size_t)gm * 128 + cg);
                v0 = p[0];
                v1 = p[1];
            }
            float f[8] = {v0.x, v0.y, v0.z, v0.w, v1.x, v1.y, v1.z, v1.w};
            __nv_bfloat16 hi[8], lo[8];
            #pragma unroll
            for (int i = 0; i < 8; i++) {
                hi[i] = __float2bfloat16(f[i]);
                lo[i] = __float2bfloat16(f[i] - __bfloat162float(hi[i]));
            }
            *(uint4*)(sAhi + r * LDS + cg) = *(uint4*)hi;
            *(uint4*)(sAlo + r * LDS + cg) = *(uint4*)lo;
        }
    }
    // ---- W tiles: on-the-fly (combine +) scale + split ----
    #pragma unroll
    for (int r = tid >> 4; r < BN; r += 16) {
        const float4* p = (const float4*)(W + (size_t)r * 128 + cg);
        float4 v0 = p[0];
        float4 v1 = p[1];
        if (W2) {
            const float4* q = (const float4*)(W2 + (size_t)r * 128 + cg);
            float4 u0 = q[0], u1 = q[1];
            v0.x += u0.x; v0.y += u0.y; v0.z += u0.z; v0.w += u0.w;
            v1.x += u1.x; v1.y += u1.y; v1.z += u1.z; v1.w += u1.w;
        }
        float f[8] = {v0.x, v0.y, v0.z, v0.w, v1.x, v1.y, v1.z, v1.w};
        __nv_bfloat16 hi[8], lo[8];
        #pragma unroll
        for (int i = 0; i < 8; i++) {
            const float sv = alpha * f[i];
            hi[i] = __float2bfloat16(sv);
            lo[i] = __float2bfloat16(sv - __bfloat162float(hi[i]));
        }
        *(uint4*)(sWhi + r * LDS + cg) = *(uint4*)hi;
        *(uint4*)(sWlo + r * LDS + cg) = *(uint4*)lo;
    }
    __syncthreads();

    // ---- warp-tiled mma mainloop ----
    const int wm = (wid % MW) * (MT * 16);
    const int wn = (wid / MW) * 32;

    float acc[MT][4][4];
    #pragma unroll
    for (int mt = 0; mt < MT; mt++)
        #pragma unroll
        for (int nt = 0; nt < 4; nt++)
            #pragma unroll
            for (int j = 0; j < 4; j++) acc[mt][nt][j] = 0.f;

    const uint32_t aAhi = smem_u32(sAhi);
    const uint32_t aAlo = smem_u32(sAlo);
    const uint32_t aWhi = smem_u32(sWhi);
    const uint32_t aWlo = smem_u32(sWlo);

    const int arow  = lane & 15;
    const int acol8 = (lane >> 4) * 8;
    const int brow  = (lane & 7) + ((lane >> 4) << 3);
    const int bcol8 = ((lane >> 3) & 1) * 8;

    #pragma unroll
    for (int k = 0; k < 8; k++) {
        const int kc = k * 16;
        uint32_t ahi[MT][4], alo[MT][4];
        #pragma unroll
        for (int mt = 0; mt < MT; mt++) {
            const uint32_t off =
                (uint32_t)((wm + mt * 16 + arow) * LDS + kc + acol8) * 2;
            ldmx4(ahi[mt], aAhi + off);
            ldmx4(alo[mt], aAlo + off);
        }
        #pragma unroll
        for (int np = 0; np < 2; np++) {
            const uint32_t boff =
                (uint32_t)((wn + np * 16 + brow) * LDS + kc + bcol8) * 2;
            uint32_t bhi[4], blo[4];
            ldmx4(bhi, aWhi + boff);
            ldmx4(blo, aWlo + boff);
            #pragma unroll
            for (int mt = 0; mt < MT; mt++) {
                #pragma unroll
                for (int h = 0; h < 2; h++) {
                    float* c = acc[mt][np * 2 + h];
                    mma16816(c, ahi[mt], bhi[2 * h], bhi[2 * h + 1]);
                    mma16816(c, alo[mt], bhi[2 * h], bhi[2 * h + 1]);
                    mma16816(c, ahi[mt], blo[2 * h], blo[2 * h + 1]);
                }
            }
        }
    }

    // ---- epilogue ----
    #pragma unroll
    for (int mt = 0; mt < MT; mt++) {
        const int r0 = m0 + wm + mt * 16 + (lane >> 2);
        #pragma unroll
        for (int nt = 0; nt < 4; nt++) {
            const int col = wn + nt * 8 + (lane & 3) * 2;
            const float* c = acc[mt][nt];
            #pragma unroll
            for (int h = 0; h < 2; h++) {
                const int gm = r0 + h * 8;
                if (gm < M) {
                    float vx = c[2 * h], vy = c[2 * h + 1];
                    if (b1) {
                        float bx = b1[col], by = b1[col + 1];
                        if (b2) { bx += b2[col]; by += b2[col + 1]; }
                        vx += bs * bx;
                        vy += bs * by;
                    }
                    if (outHalf) {
                        *(__half2*)((__half*)C + (size_t)gm * BN + col) =
                            __floats2half2_rn(vx, vy);
                    } else {
                        *(float2*)((float*)C + (size_t)gm * BN + col) =
                            make_float2(vx, vy);
                    }
                }
            }
        }
    }
    __syncthreads();   // smem reuse safety before next tile's fill
}

// ------------------------------ gathers -------------------------------------
__device__ __forceinline__ void acc_rel128(int b, int e, int lane,
                                           const __half* __restrict__ y,
                                           float* res) {
    float acc[4] = {0.f, 0.f, 0.f, 0.f};
    int i = b;
    for (; i + 3 < e; i += 4) {
        #pragma unroll
        for (int k = 0; k < 4; k++) {
            const int s = __ldg(&g_src[i + k]);
            uint2 u = *(const uint2*)(y + (size_t)s * 128 + lane * 4);
            float2 a0 = __half22float2(*(const __half2*)&u.x);
            float2 a1 = __half22float2(*(const __half2*)&u.y);
            acc[0] += a0.x; acc[1] += a0.y; acc[2] += a1.x; acc[3] += a1.y;
        }
    }
    for (; i < e; i++) {
        const int s = __ldg(&g_src[i]);
        uint2 u = *(const uint2*)(y + (size_t)s * 128 + lane * 4);
        float2 a0 = __half22float2(*(const __half2*)&u.x);
        float2 a1 = __half22float2(*(const __half2*)&u.y);
        acc[0] += a0.x; acc[1] += a0.y; acc[2] += a1.x; acc[3] += a1.y;
    }
    const int deg = e - b;
    const float inv = deg > 0 ? 1.f / (float)deg : 0.f;
    #pragma unroll
    for (int v = 0; v < 4; v++) res[v] += acc[v] * inv;
}

__device__ void gather1_node(int gw, int lane) {
    float res[4] = {0.f, 0.f, 0.f, 0.f};
    const float* S;
    __nv_bfloat16 *oh, *ol;
    int node;
    if (gw < NPn) {
        node = gw;
        acc_rel128(g_off[gw], g_off[gw + 1], lane, g_yah, res);
        acc_rel128(g_off[NPn + gw], g_off[NPn + gw + 1], lane, g_yph, res);
        S = g_S1p; oh = g_hp1h; ol = g_hp1l;
    } else {
        node = gw - NPn;
        acc_rel128(g_off[2 * NPn + node], g_off[2 * NPn + node + 1], lane, g_yrh, res);
        S = g_S1a; oh = g_ha1h; ol = g_ha1l;
    }
    float4 s4 = *(const float4*)(S + (size_t)node * 128 + lane * 4);
    float v[4] = {fmaxf(s4.x + res[0], 0.f), fmaxf(s4.y + res[1], 0.f),
                  fmaxf(s4.z + res[2], 0.f), fmaxf(s4.w + res[3], 0.f)};
    __nv_bfloat16 hi[4], lo[4];
    #pragma unroll
    for (int k = 0; k < 4; k++) {
        hi[k] = __float2bfloat16(v[k]);
        lo[k] = __float2bfloat16(v[k] - __bfloat162float(hi[k]));
    }
    *(uint2*)(oh + (size_t)node * 128 + lane * 4) = *(uint2*)hi;
    *(uint2*)(ol + (size_t)node * 128 + lane * 4) = *(uint2*)lo;
}

__device__ void gather2_node(int gw, int lane, float* __restrict__ out) {
    float res[2] = {0.f, 0.f};
    #pragma unroll
    for (int rel = 0; rel < 2; rel++) {
        const __half* y = rel ? g_zph : g_zah;
        const int b = g_off[rel * NPn + gw];
        const int e = g_off[rel * NPn + gw + 1];
        float acc0 = 0.f, acc1 = 0.f;
        int i = b;
        for (; i + 3 < e; i += 4) {
            #pragma unroll
            for (int k = 0; k < 4; k++) {
                const int s = __ldg(&g_src[i + k]);
                float2 a = __half22float2(*(const __half2*)(y + (size_t)s * 64 + lane * 2));
                acc0 += a.x; acc1 += a.y;
            }
        }
        for (; i < e; i++) {
            const int s = __ldg(&g_src[i]);
            float2 a = __half22float2(*(const __half2*)(y + (size_t)s * 64 + lane * 2));
            acc0 += a.x; acc1 += a.y;
        }
        const int deg = e - b;
        const float inv = deg > 0 ? 1.f / (float)deg : 0.f;
        res[0] += acc0 * inv;
        res[1] += acc1 * inv;
    }
    float2 s2 = *(const float2*)(g_S2 + (size_t)gw * 64 + lane * 2);
    *(float2*)(out + (size_t)gw * 64 + lane * 2) =
        make_float2(s2.x + res[0], s2.y + res[1]);
}

// ----------------------------- mega kernel -----------------------------------
__global__ void __launch_bounds__(256, 2)
mega_kernel(const float* __restrict__ xp, const float* __restrict__ xa,
            const float* __restrict__ Wl1, const float* __restrict__ bl1,
            const float* __restrict__ Wr1, const float* __restrict__ Wl2,
            const float* __restrict__ bl2, const float* __restrict__ Wr2,
            const int* wsrc, const int* wdst, const int* csrc, const int* cdst,
            const int* rsrc, const int* rdst, float* __restrict__ out) {
    extern __shared__ __align__(16) char smemRaw[];
    int* s_item = (int*)(smemRaw + SMEM_MAIN);
    const int bId = blockIdx.x;
    const int tid = threadIdx.x;
    const int lane = tid & 31;
    const int wid  = tid >> 5;

    // graph CTAs build the CSR first, then join the GEMM queue
    if (bId < GC)
        graph_program(bId, smemRaw, wsrc, wdst, csrc, cdst, rsrc, rdst);

    // ---- stage 1: L1 GEMMs (dynamic queue 0) ----
    for (;;) {
        __syncthreads();
        if (tid == 0) *s_item = (int)atomicAdd(&g_q[0], 1u);
        __syncthreads();
        const int tile = *s_item;
        if (tile >= S1E4) break;
        if (tile < S1E0) {
            gemm_tile<128>(smemRaw, tile * 64, NAn, xa, nullptr,
                           Wl1, nullptr, 0.5f, g_yah, 1, nullptr, nullptr, 0.f);
        } else if (tile < S1E1) {
            gemm_tile<128>(smemRaw, (tile - S1E0) * 64, NPn, xp, nullptr,
                           Wl1 + 16384, nullptr, 0.5f, g_yph, 1, nullptr, nullptr, 0.f);
        } else if (tile < S1E2) {
            gemm_tile<128>(smemRaw, (tile - S1E1) * 64, NPn, xp, nullptr,
                           Wl1 + 32768, nullptr, 1.0f, g_yrh, 1, nullptr, nullptr, 0.f);
        } else if (tile < S1E3) {
            gemm_tile<128>(smemRaw, (tile - S1E2) * 64, NPn, xp, nullptr,
                           Wr1, Wr1 + 16384, 0.5f, g_S1p, 0, bl1, bl1 + 128, 0.5f);
        } else {
            gemm_tile<128>(smemRaw, (tile - S1E3) * 64, NAn, xa, nullptr,
                           Wr1 + 32768, nullptr, 1.0f, g_S1a, 0, bl1 + 256, nullptr, 1.0f);
        }
    }
    gbar(0, NCTA);

    // ---- stage 2: L1 gather (queue 1; 64 nodes per pop, 8 per warp) ----
    for (;;) {
        __syncthreads();
        if (tid == 0) *s_item = (int)atomicAdd(&g_q[1], 1u);
        __syncthreads();
        const int u = *s_item;
        if (u >= NG1) break;
        const int n0 = u * 64 + wid * 8;
        #pragma unroll
        for (int j = 0; j < 8; j++) {
            const int gw = n0 + j;
            if (gw < NPn + NAn) gather1_node(gw, lane);
        }
    }
    gbar(1, NCTA);

    // ---- stage 3: L2 GEMMs (queue 2) ----
    for (;;) {
        __syncthreads();
        if (tid == 0) *s_item = (int)atomicAdd(&g_q[2], 1u);
        __syncthreads();
        const int tile = *s_item;
        if (tile >= S3E2) break;
        if (tile < S3E0) {
            gemm_tile<64>(smemRaw, tile * 64, NAn, g_ha1h, g_ha1l,
                          Wl2, nullptr, 0.5f, g_zah, 1, nullptr, nullptr, 0.f);
        } else if (tile < S3E1) {
            gemm_tile<64>(smemRaw, (tile - S3E0) * 64, NPn, g_hp1h, g_hp1l,
                          Wl2 + 8192, nullptr, 0.5f, g_zph, 1, nullptr, nullptr, 0.f);
        } else {
            gemm_tile<64>(smemRaw, (tile - S3E1) * 64, NPn, g_hp1h, g_hp1l,
                          Wr2, Wr2 + 8192, 0.5f, g_S2, 0, bl2, bl2 + 64, 0.5f);
        }
    }
    gbar(2, NCTA);

    // ---- stage 4: L2 gather -> out (queue 3) ----
    for (;;) {
        __syncthreads();
        if (tid == 0) *s_item = (int)atomicAdd(&g_q[3], 1u);
        __syncthreads();
        const int u = *s_item;
        if (u >= NG2) break;
        const int n0 = u * 64 + wid * 8;
        #pragma unroll
        for (int j = 0; j < 8; j++) {
            const int gw = n0 + j;
            if (gw < NPn) gather2_node(gw, lane, out);
        }
    }
    gbar(3, NCTA);

    // reset work queues for the next graph replay (stream-ordered: safe)
    if (bId == 0 && tid < 4) g_q[tid] = 0;
}

// ------------------------------- launch -------------------------------------
extern "C" void kernel_launch(void* const* d_in, const int* in_sizes, int n_in,
                              void* d_out, int out_size) {
    const float* xp  = (const float*)d_in[0];
    const float* xa  = (const float*)d_in[1];
    const float* Wl1 = (const float*)d_in[2];
    const float* bl1 = (const float*)d_in[3];
    const float* Wr1 = (const float*)d_in[4];
    const float* Wl2 = (const float*)d_in[5];
    const float* bl2 = (const float*)d_in[6];
    const float* Wr2 = (const float*)d_in[7];
    const int* wsrc = (const int*)d_in[8];
    const int* wdst = (const int*)d_in[9];
    const int* csrc = (const int*)d_in[10];
    const int* cdst = (const int*)d_in[11];
    const int* rsrc = (const int*)d_in[12];
    const int* rdst = (const int*)d_in[13];
    float* out = (float*)d_out;

    cudaFuncSetAttribute((const void*)mega_kernel,
                         cudaFuncAttributeMaxDynamicSharedMemorySize, SMEM_TOT);

    mega_kernel<<<NCTA, 256, SMEM_TOT>>>(
        xp, xa, Wl1, bl1, Wr1, Wl2, bl2, Wr2,
        wsrc, wdst, csrc, cdst, rsrc, rdst, out);
}

// round 15
// speedup vs baseline: 1.6544x; 1.6544x over previous
#include <cuda_runtime.h>
#include <cuda_bf16.h>
#include <cuda_fp16.h>
#include <cstdint>

// ---------------------------------------------------------------------------
// RSAGE_Hetero round 13: REVERT to round-9 structure (best, 207.3us), plus:
//  - L2: zph+S2 merged into ONE BN=128 GEMM over concatenated weights
//    (split epilogue: cols 0-63 -> fp16 zph, 64-127 -> fp32 S2 + bias)
//  - zah task rides the same BN=128 launch with a zero-padded weight half
//  5 launches, all other code identical to round 9.
// ---------------------------------------------------------------------------

constexpr int NPn  = 50000;
constexpr int NAn  = 20000;
constexpr int DH   = 128;
constexpr int DOUT = 64;
constexpr int EWn  = 250000;
constexpr int ECn  = 500000;
constexpr int ERn  = 250000;
constexpr int NT   = 2 * NPn + NAn;      // 120000
constexpr int ET   = EWn + ECn + ERn;    // 1,000,000
constexpr int GC   = 144;                // graph CTAs

// pre-split weight segments (bf16 hi/lo), 128 elems per row, alpha folded
constexpr int OFF_W1P  = 0;              // 0.5*Wl1[1]        [128x128]
constexpr int OFF_W1R  = 16384;          //     Wl1[2]        [128x128]
constexpr int OFF_WC1  = 32768;          // 0.5*(Wr1[0]+Wr1[1])
constexpr int OFF_W1A  = 49152;          // 0.5*Wl1[0]
constexpr int OFF_WR1A = 65536;          //     Wr1[2]
constexpr int OFF_W2PC = 81920;          // [0.5*Wl2[1] ; 0.5*(Wr2[0]+Wr2[1])] [128x128]
constexpr int OFF_W2AZ = 98304;          // [0.5*Wl2[0] ; zeros]               [128x128]
constexpr int WTOT     = 114688;

// ------------------------------ scratch ------------------------------------
__device__ __half g_yah[NAn * DH];
__device__ __half g_yph[NPn * DH];
__device__ __half g_yrh[NPn * DH];
__device__ __half g_zah[NAn * DOUT];
__device__ __half g_zph[NPn * DOUT];
__device__ float  g_S1p[NPn * DH];
__device__ float  g_S1a[NAn * DH];
__device__ float  g_S2 [NPn * DOUT];
__device__ __nv_bfloat16 g_hp1h[NPn * DH], g_hp1l[NPn * DH];
__device__ __nv_bfloat16 g_ha1h[NAn * DH], g_ha1l[NAn * DH];

__device__ __nv_bfloat16 g_Wh[WTOT], g_Wl[WTOT];
__device__ float g_bc1[DH];
__device__ float g_bc2[DOUT];

__device__ int g_deg[NT], g_off[NT + 1], g_cur[NT], g_src[ET];
__device__ int g_bsum[GC], g_bbase[GC];
__device__ int g_bar[4];

// --------------------------- PTX helpers -----------------------------------
__device__ __forceinline__ uint32_t smem_u32(const void* p) {
    uint32_t a;
    asm("{ .reg .u64 t; cvta.to.shared.u64 t, %1; cvt.u32.u64 %0, t; }"
        : "=r"(a) : "l"(p));
    return a;
}

__device__ __forceinline__ void ldmx4(uint32_t* r, uint32_t addr) {
    asm volatile(
        "ldmatrix.sync.aligned.m8n8.x4.shared.b16 {%0,%1,%2,%3}, [%4];"
        : "=r"(r[0]), "=r"(r[1]), "=r"(r[2]), "=r"(r[3]) : "r"(addr));
}

__device__ __forceinline__ void mma16816(float* c, const uint32_t* a,
                                         uint32_t b0, uint32_t b1) {
    asm volatile(
        "mma.sync.aligned.m16n8k16.row.col.f32.bf16.bf16.f32 "
        "{%0,%1,%2,%3}, {%4,%5,%6,%7}, {%8,%9}, {%0,%1,%2,%3};"
        : "+f"(c[0]), "+f"(c[1]), "+f"(c[2]), "+f"(c[3])
        : "r"(a[0]), "r"(a[1]), "r"(a[2]), "r"(a[3]), "r"(b0), "r"(b1));
}

__device__ __forceinline__ void graph_bar(int idx) {
    __syncthreads();
    if (threadIdx.x == 0) {
        __threadfence();
        atomicAdd(&g_bar[idx], 1);
        while (*(volatile int*)&g_bar[idx] < GC) __nanosleep(64);
    }
    __syncthreads();
    __threadfence();
}

// --------------------------- setup: zero + weight pre-split -----------------
__global__ void zero_prep_kernel(const float* __restrict__ Wl1,
                                 const float* __restrict__ bl1,
                                 const float* __restrict__ Wr1,
                                 const float* __restrict__ Wl2,
                                 const float* __restrict__ bl2,
                                 const float* __restrict__ Wr2) {
    int i = blockIdx.x * blockDim.x + threadIdx.x;
    if (i < NT) g_deg[i] = 0;
    if (i < 4)  g_bar[i] = 0;
    if (i == 0) g_off[NT] = ET;
    if (i < DH)   g_bc1[i] = 0.5f * (bl1[i] + bl1[DH + i]);
    if (i < DOUT) g_bc2[i] = 0.5f * (bl2[i] + bl2[DOUT + i]);

    if (i < WTOT) {
        float v;
        if (i < OFF_W1R)       v = 0.5f * Wl1[16384 + i];
        else if (i < OFF_WC1)  v = Wl1[32768 + (i - OFF_W1R)];
        else if (i < OFF_W1A)  { int j = i - OFF_WC1; v = 0.5f * (Wr1[j] + Wr1[16384 + j]); }
        else if (i < OFF_WR1A) v = 0.5f * Wl1[i - OFF_W1A];
        else if (i < OFF_W2PC) v = Wr1[32768 + (i - OFF_WR1A)];
        else if (i < OFF_W2AZ) {
            int j = i - OFF_W2PC;          // [128x128]: rows 0-63 zph-W, 64-127 S2-W
            int r = j >> 7, c = j & 127;
            if (r < 64) v = 0.5f * Wl2[8192 + r * 128 + c];
            else {
                int rr = r - 64;
                v = 0.5f * (Wr2[rr * 128 + c] + Wr2[8192 + rr * 128 + c]);
            }
        } else {
            int j = i - OFF_W2AZ;          // rows 0-63 zah-W, 64-127 zeros
            int r = j >> 7, c = j & 127;
            v = (r < 64) ? 0.5f * Wl2[r * 128 + c] : 0.f;
        }
        __nv_bfloat16 hi = __float2bfloat16(v);
        g_Wh[i] = hi;
        g_Wl[i] = __float2bfloat16(v - __bfloat162float(hi));
    }
}

// --------------------------- graph CTA program (256 threads) ----------------
__device__ void graph_cta(int c, char* smemRaw,
                          const int* wsrc, const int* wdst,
                          const int* csrc, const int* cdst,
                          const int* rsrc, const int* rdst) {
    int* s = (int*)smemRaw;
    const int tid = threadIdx.x;
    const int tg = c * 256 + tid;
    const int stride = GC * 256;

    for (int i = tg; i < EWn / 4; i += stride) {
        int4 d = ((const int4*)wdst)[i];
        atomicAdd(&g_deg[d.x], 1); atomicAdd(&g_deg[d.y], 1);
        atomicAdd(&g_deg[d.z], 1); atomicAdd(&g_deg[d.w], 1);
    }
    for (int i = tg; i < ECn / 4; i += stride) {
        int4 d = ((const int4*)cdst)[i];
        atomicAdd(&g_deg[NPn + d.x], 1); atomicAdd(&g_deg[NPn + d.y], 1);
        atomicAdd(&g_deg[NPn + d.z], 1); atomicAdd(&g_deg[NPn + d.w], 1);
    }
    for (int i = tg; i < ERn / 4; i += stride) {
        int4 d = ((const int4*)rdst)[i];
        atomicAdd(&g_deg[2 * NPn + d.x], 1); atomicAdd(&g_deg[2 * NPn + d.y], 1);
        atomicAdd(&g_deg[2 * NPn + d.z], 1); atomicAdd(&g_deg[2 * NPn + d.w], 1);
    }
    graph_bar(0);

    const int i0 = c * 1024 + tid * 4;
    int e[4];
    int tsum = 0;
    #pragma unroll
    for (int k = 0; k < 4; k++) {
        e[k] = (i0 + k < NT) ? g_deg[i0 + k] : 0;
        tsum += e[k];
    }
    s[tid] = tsum;
    __syncthreads();
    #pragma unroll
    for (int d = 1; d < 256; d <<= 1) {
        int v = (tid >= d) ? s[tid - d] : 0;
        __syncthreads();
        s[tid] += v;
        __syncthreads();
    }
    const int pre = s[tid] - tsum;
    if (tid == 255) g_bsum[c] = s[255];
    graph_bar(1);

    if (c == 0) {
        int v = (tid < GC) ? g_bsum[tid] : 0;
        s[tid] = v;
        __syncthreads();
        #pragma unroll
        for (int d = 1; d < 256; d <<= 1) {
            int t = (tid >= d) ? s[tid - d] : 0;
            __syncthreads();
            s[tid] += t;
            __syncthreads();
        }
        if (tid < GC) g_bbase[tid] = s[tid] - v;
    }
    graph_bar(2);

    {
        int run = g_bbase[c] + pre;
        #pragma unroll
        for (int k = 0; k < 4; k++) {
            if (i0 + k < NT) {
                g_off[i0 + k] = run;
                g_cur[i0 + k] = run;
                run += e[k];
            }
        }
    }
    graph_bar(3);

    for (int i = tg; i < EWn / 4; i += stride) {
        int4 d = ((const int4*)wdst)[i];
        int4 sv = ((const int4*)wsrc)[i];
        g_src[atomicAdd(&g_cur[d.x], 1)] = sv.x;
        g_src[atomicAdd(&g_cur[d.y], 1)] = sv.y;
        g_src[atomicAdd(&g_cur[d.z], 1)] = sv.z;
        g_src[atomicAdd(&g_cur[d.w], 1)] = sv.w;
    }
    for (int i = tg; i < ECn / 4; i += stride) {
        int4 d = ((const int4*)cdst)[i];
        int4 sv = ((const int4*)csrc)[i];
        g_src[atomicAdd(&g_cur[NPn + d.x], 1)] = sv.x;
        g_src[atomicAdd(&g_cur[NPn + d.y], 1)] = sv.y;
        g_src[atomicAdd(&g_cur[NPn + d.z], 1)] = sv.z;
        g_src[atomicAdd(&g_cur[NPn + d.w], 1)] = sv.w;
    }
    for (int i = tg; i < ERn / 4; i += stride) {
        int4 d = ((const int4*)rdst)[i];
        int4 sv = ((const int4*)rsrc)[i];
        g_src[atomicAdd(&g_cur[2 * NPn + d.x], 1)] = sv.x;
        g_src[atomicAdd(&g_cur[2 * NPn + d.y], 1)] = sv.y;
        g_src[atomicAdd(&g_cur[2 * NPn + d.z], 1)] = sv.z;
        g_src[atomicAdd(&g_cur[2 * NPn + d.w], 1)] = sv.w;
    }
}

// ---------------------- flat per-task GEMM, BM=64, 256 threads ---------------
// modes: 0 = full BN cols -> half C0
//        1 = full BN cols -> float C0 + bias
//        2 = split: cols<64 -> half C0 (stride 64); cols>=64 -> float C1 + bias (stride 64)
//        3 = split lo only: cols<64 -> half C0 (stride 64)
struct GTask {
    const void* A;         // fp32 rows, or bf16 hi rows if Alo != null
    const void* Alo;       // bf16 lo rows
    int woff;              // offset into g_Wh/g_Wl
    void* C0;
    void* C1;
    const float* bias;     // nullable
    int M;
    int ctaEnd;            // absolute
    int mode;
};

template <int BN>
__global__ void __launch_bounds__(256, 2)
tc_mega(GTask t0, GTask t1, GTask t2, GTask t3, GTask t4, int gc,
        const int* wsrc, const int* wdst, const int* csrc, const int* cdst,
        const int* rsrc, const int* rdst) {
    constexpr int LDS = 136;
    constexpr int BM  = 64;
    constexpr int MT  = (BN == 128) ? 2 : 1;   // m16 tiles per warp
    constexpr int MW  = (BN == 128) ? 2 : 4;   // warps along m

    extern __shared__ __align__(16) char smemRaw[];
    const int bId = blockIdx.x;

    if (bId < gc) {
        graph_cta(bId, smemRaw, wsrc, wdst, csrc, cdst, rsrc, rdst);
        return;
    }

    GTask t;
    int base;
    if (bId < t0.ctaEnd)      { t = t0; base = gc; }
    else if (bId < t1.ctaEnd) { t = t1; base = t0.ctaEnd; }
    else if (bId < t2.ctaEnd) { t = t2; base = t1.ctaEnd; }
    else if (bId < t3.ctaEnd) { t = t3; base = t2.ctaEnd; }
    else                      { t = t4; base = t3.ctaEnd; }

    __nv_bfloat16* sm  = (__nv_bfloat16*)smemRaw;
    __nv_bfloat16* sAhi = sm;
    __nv_bfloat16* sAlo = sAhi + BM * LDS;
    __nv_bfloat16* sWhi = sAlo + BM * LDS;
    __nv_bfloat16* sWlo = sWhi + BN * LDS;

    const int tid  = threadIdx.x;
    const int lane = tid & 31;
    const int wid  = tid >> 5;
    const int m0   = (bId - base) * BM;
    const int M    = t.M;
    const int cg   = (tid & 15) * 8;

    // ---- A tile (64 rows) ----
    if (t.Alo) {
        const __nv_bfloat16* Ah = (const __nv_bfloat16*)t.A;
        const __nv_bfloat16* Al = (const __nv_bfloat16*)t.Alo;
        #pragma unroll
        for (int r = tid >> 4; r < BM; r += 16) {
            const int gm = m0 + r;
            uint4 vh = make_uint4(0, 0, 0, 0), vl = vh;
            if (gm < M) {
                vh = *(const uint4*)(Ah + (size_t)gm * 128 + cg);
                vl = *(const uint4*)(Al + (size_t)gm * 128 + cg);
            }
            *(uint4*)(sAhi + r * LDS + cg) = vh;
            *(uint4*)(sAlo + r * LDS + cg) = vl;
        }
    } else {
        const float* A = (const float*)t.A;
        #pragma unroll
        for (int r = tid >> 4; r < BM; r += 16) {
            const int gm = m0 + r;
            float4 v0 = make_float4(0.f, 0.f, 0.f, 0.f), v1 = v0;
            if (gm < M) {
                const float4* p = (const float4*)(A + (size_t)gm * 128 + cg);
                v0 = p[0];
                v1 = p[1];
            }
            float f[8] = {v0.x, v0.y, v0.z, v0.w, v1.x, v1.y, v1.z, v1.w};
            __nv_bfloat16 hi[8], lo[8];
            #pragma unroll
            for (int i = 0; i < 8; i++) {
                hi[i] = __float2bfloat16(f[i]);
                lo[i] = __float2bfloat16(f[i] - __bfloat162float(hi[i]));
            }
            *(uint4*)(sAhi + r * LDS + cg) = *(uint4*)hi;
            *(uint4*)(sAlo + r * LDS + cg) = *(uint4*)lo;
        }
    }
    // ---- W tiles (pre-split: pure copy) ----
    {
        const __nv_bfloat16* gh = g_Wh + t.woff;
        const __nv_bfloat16* gl = g_Wl + t.woff;
        #pragma unroll
        for (int r = tid >> 4; r < BN; r += 16) {
            *(uint4*)(sWhi + r * LDS + cg) = *(const uint4*)(gh + r * 128 + cg);
            *(uint4*)(sWlo + r * LDS + cg) = *(const uint4*)(gl + r * 128 + cg);
        }
    }
    __syncthreads();

    // ---- warp-tiled mma mainloop ----
    const int wm = (wid % MW) * (MT * 16);
    const int wn = (wid / MW) * 32;

    float acc[MT][4][4];
    #pragma unroll
    for (int mt = 0; mt < MT; mt++)
        #pragma unroll
        for (int nt = 0; nt < 4; nt++)
            #pragma unroll
            for (int j = 0; j < 4; j++) acc[mt][nt][j] = 0.f;

    const uint32_t aAhi = smem_u32(sAhi);
    const uint32_t aAlo = smem_u32(sAlo);
    const uint32_t aWhi = smem_u32(sWhi);
    const uint32_t aWlo = smem_u32(sWlo);

    const int arow  = lane & 15;
    const int acol8 = (lane >> 4) * 8;
    const int brow  = (lane & 7) + ((lane >> 4) << 3);
    const int bcol8 = ((lane >> 3) & 1) * 8;

    #pragma unroll
    for (int k = 0; k < 8; k++) {
        const int kc = k * 16;
        uint32_t ahi[MT][4], alo[MT][4];
        #pragma unroll
        for (int mt = 0; mt < MT; mt++) {
            const uint32_t off =
                (uint32_t)((wm + mt * 16 + arow) * LDS + kc + acol8) * 2;
            ldmx4(ahi[mt], aAhi + off);
            ldmx4(alo[mt], aAlo + off);
        }
        #pragma unroll
        for (int np = 0; np < 2; np++) {
            const uint32_t boff =
                (uint32_t)((wn + np * 16 + brow) * LDS + kc + bcol8) * 2;
            uint32_t bhi[4], blo[4];
            ldmx4(bhi, aWhi + boff);
            ldmx4(blo, aWlo + boff);
            #pragma unroll
            for (int mt = 0; mt < MT; mt++) {
                #pragma unroll
                for (int h = 0; h < 2; h++) {
                    float* c = acc[mt][np * 2 + h];
                    mma16816(c, ahi[mt], bhi[2 * h], bhi[2 * h + 1]);
                    mma16816(c, alo[mt], bhi[2 * h], bhi[2 * h + 1]);
                    mma16816(c, ahi[mt], blo[2 * h], blo[2 * h + 1]);
                }
            }
        }
    }

    // ---- epilogue ----
    #pragma unroll
    for (int mt = 0; mt < MT; mt++) {
        const int r0 = m0 + wm + mt * 16 + (lane >> 2);
        #pragma unroll
        for (int nt = 0; nt < 4; nt++) {
            const int col = wn + nt * 8 + (lane & 3) * 2;
            const float* c = acc[mt][nt];
            #pragma unroll
            for (int h = 0; h < 2; h++) {
                const int gm = r0 + h * 8;
                if (gm >= M) continue;
                float vx = c[2 * h], vy = c[2 * h + 1];
                if (t.mode == 0) {
                    *(__half2*)((__half*)t.C0 + (size_t)gm * BN + col) =
                        __floats2half2_rn(vx, vy);
                } else if (t.mode == 1) {
                    vx += t.bias[col]; vy += t.bias[col + 1];
                    *(float2*)((float*)t.C0 + (size_t)gm * BN + col) =
                        make_float2(vx, vy);
                } else if (col < 64) {          // modes 2,3: low half -> fp16
                    *(__half2*)((__half*)t.C0 + (size_t)gm * 64 + col) =
                        __floats2half2_rn(vx, vy);
                } else if (t.mode == 2) {       // high half -> fp32 + bias
                    const int cc = col - 64;
                    vx += t.bias[cc]; vy += t.bias[cc + 1];
                    *(float2*)((float*)t.C1 + (size_t)gm * 64 + cc) =
                        make_float2(vx, vy);
                }
            }
        }
    }
}

// ------------------------------ gathers -------------------------------------
__device__ __forceinline__ void acc_rel128(int b, int e, int lane,
                                           const __half* __restrict__ y,
                                           float* res) {
    float acc[4] = {0.f, 0.f, 0.f, 0.f};
    int i = b;
    for (; i + 3 < e; i += 4) {
        #pragma unroll
        for (int k = 0; k < 4; k++) {
            const int s = __ldg(&g_src[i + k]);
            uint2 u = *(const uint2*)(y + (size_t)s * 128 + lane * 4);
            float2 a0 = __half22float2(*(const __half2*)&u.x);
            float2 a1 = __half22float2(*(const __half2*)&u.y);
            acc[0] += a0.x; acc[1] += a0.y; acc[2] += a1.x; acc[3] += a1.y;
        }
    }
    for (; i < e; i++) {
        const int s = __ldg(&g_src[i]);
        uint2 u = *(const uint2*)(y + (size_t)s * 128 + lane * 4);
        float2 a0 = __half22float2(*(const __half2*)&u.x);
        float2 a1 = __half22float2(*(const __half2*)&u.y);
        acc[0] += a0.x; acc[1] += a0.y; acc[2] += a1.x; acc[3] += a1.y;
    }
    const int deg = e - b;
    const float inv = deg > 0 ? 1.f / (float)deg : 0.f;
    #pragma unroll
    for (int v = 0; v < 4; v++) res[v] += acc[v] * inv;
}

__global__ void gather_l1_kernel() {
    const int gw   = (blockIdx.x * blockDim.x + threadIdx.x) >> 5;
    const int lane = threadIdx.x & 31;
    float res[4] = {0.f, 0.f, 0.f, 0.f};
    const float* S;
    __nv_bfloat16 *oh, *ol;
    int node;
    if (gw < NPn) {
        node = gw;
        acc_rel128(g_off[gw], g_off[gw + 1], lane, g_yah, res);
        acc_rel128(g_off[NPn + gw], g_off[NPn + gw + 1], lane, g_yph, res);
        S = g_S1p; oh = g_hp1h; ol = g_hp1l;
    } else if (gw < NPn + NAn) {
        node = gw - NPn;
        acc_rel128(g_off[2 * NPn + node], g_off[2 * NPn + node + 1], lane, g_yrh, res);
        S = g_S1a; oh = g_ha1h; ol = g_ha1l;
    } else {
        return;
    }
    float4 s4 = *(const float4*)(S + (size_t)node * 128 + lane * 4);
    float v[4] = {fmaxf(s4.x + res[0], 0.f), fmaxf(s4.y + res[1], 0.f),
                  fmaxf(s4.z + res[2], 0.f), fmaxf(s4.w + res[3], 0.f)};
    __nv_bfloat16 hi[4], lo[4];
    #pragma unroll
    for (int k = 0; k < 4; k++) {
        hi[k] = __float2bfloat16(v[k]);
        lo[k] = __float2bfloat16(v[k] - __bfloat162float(hi[k]));
    }
    *(uint2*)(oh + (size_t)node * 128 + lane * 4) = *(uint2*)hi;
    *(uint2*)(ol + (size_t)node * 128 + lane * 4) = *(uint2*)lo;
}

__global__ void gather_l2_kernel(float* __restrict__ out) {
    const int gw   = (blockIdx.x * blockDim.x + threadIdx.x) >> 5;
    const int lane = threadIdx.x & 31;
    if (gw >= NPn) return;

    float res[2] = {0.f, 0.f};
    #pragma unroll
    for (int rel = 0; rel < 2; rel++) {
        const __half* y = rel ? g_zph : g_zah;
        const int b = g_off[rel * NPn + gw];
        const int e = g_off[rel * NPn + gw + 1];
        float acc0 = 0.f, acc1 = 0.f;
        int i = b;
        for (; i + 3 < e; i += 4) {
            #pragma unroll
            for (int k = 0; k < 4; k++) {
                const int s = __ldg(&g_src[i + k]);
                float2 a = __half22float2(*(const __half2*)(y + (size_t)s * 64 + lane * 2));
                acc0 += a.x; acc1 += a.y;
            }
        }
        for (; i < e; i++) {
            const int s = __ldg(&g_src[i]);
            float2 a = __half22float2(*(const __half2*)(y + (size_t)s * 64 + lane * 2));
            acc0 += a.x; acc1 += a.y;
        }
        const int deg = e - b;
        const float inv = deg > 0 ? 1.f / (float)deg : 0.f;
        res[0] += acc0 * inv;
        res[1] += acc1 * inv;
    }
    float2 s2 = *(const float2*)(g_S2 + (size_t)gw * 64 + lane * 2);
    *(float2*)(out + (size_t)gw * 64 + lane * 2) =
        make_float2(s2.x + res[0], s2.y + res[1]);
}

// ------------------------------- launch -------------------------------------
extern "C" void kernel_launch(void* const* d_in, const int* in_sizes, int n_in,
                              void* d_out, int out_size) {
    const float* xp  = (const float*)d_in[0];
    const float* xa  = (const float*)d_in[1];
    const float* Wl1 = (const float*)d_in[2];
    const float* bl1 = (const float*)d_in[3];
    const float* Wr1 = (const float*)d_in[4];
    const float* Wl2 = (const float*)d_in[5];
    const float* bl2 = (const float*)d_in[6];
    const float* Wr2 = (const float*)d_in[7];
    const int* wsrc = (const int*)d_in[8];
    const int* wdst = (const int*)d_in[9];
    const int* csrc = (const int*)d_in[10];
    const int* cdst = (const int*)d_in[11];
    const int* rsrc = (const int*)d_in[12];
    const int* rdst = (const int*)d_in[13];
    float* out = (float*)d_out;

    __half *p_yah, *p_yph, *p_yrh, *p_zah, *p_zph;
    float *p_S1p, *p_S1a, *p_S2, *p_bc1, *p_bc2;
    __nv_bfloat16 *p_hp1h, *p_hp1l, *p_ha1h, *p_ha1l;
    cudaGetSymbolAddress((void**)&p_yah, g_yah);
    cudaGetSymbolAddress((void**)&p_yph, g_yph);
    cudaGetSymbolAddress((void**)&p_yrh, g_yrh);
    cudaGetSymbolAddress((void**)&p_zah, g_zah);
    cudaGetSymbolAddress((void**)&p_zph, g_zph);
    cudaGetSymbolAddress((void**)&p_S1p, g_S1p);
    cudaGetSymbolAddress((void**)&p_S1a, g_S1a);
    cudaGetSymbolAddress((void**)&p_S2,  g_S2);
    cudaGetSymbolAddress((void**)&p_bc1, g_bc1);
    cudaGetSymbolAddress((void**)&p_bc2, g_bc2);
    cudaGetSymbolAddress((void**)&p_hp1h, g_hp1h);
    cudaGetSymbolAddress((void**)&p_hp1l, g_hp1l);
    cudaGetSymbolAddress((void**)&p_ha1h, g_ha1h);
    cudaGetSymbolAddress((void**)&p_ha1l, g_ha1l);

    constexpr int SMEM128 = 2 * 64 * 136 * 2 + 2 * 128 * 136 * 2;  // 104448
    cudaFuncSetAttribute((const void*)tc_mega<128>,
                         cudaFuncAttributeMaxDynamicSharedMemorySize, SMEM128);

    const int gNP = (NPn + 63) / 64;   // 782
    const int gNA = (NAn + 63) / 64;   // 313

    // K1: zero + pre-split weights + biases
    zero_prep_kernel<<<(NT + 255) / 256, 256>>>(Wl1, bl1, Wr1, Wl2, bl2, Wr2);

    // K2: graph CTAs + L1 flat GEMMs (yah | yph | yrh | S1p | S1a)
    {
        int e0 = GC + gNA;
        int e1 = e0 + gNP;
        int e2 = e1 + gNP;
        int e3 = e2 + gNP;
        int e4 = e3 + gNA;
        GTask ta = {xa, nullptr, OFF_W1A,  p_yah, nullptr, nullptr,      NAn, e0, 0};
        GTask tp = {xp, nullptr, OFF_W1P,  p_yph, nullptr, nullptr,      NPn, e1, 0};
        GTask tr = {xp, nullptr, OFF_W1R,  p_yrh, nullptr, nullptr,      NPn, e2, 0};
        GTask ts = {xp, nullptr, OFF_WC1,  p_S1p, nullptr, p_bc1,        NPn, e3, 1};
        GTask tu = {xa, nullptr, OFF_WR1A, p_S1a, nullptr, bl1 + 2 * DH, NAn, e4, 1};
        tc_mega<128><<<e4, 256, SMEM128>>>(ta, tp, tr, ts, tu, GC,
                                           wsrc, wdst, csrc, cdst, rsrc, rdst);
    }

    // K3: L1 gather + relu + bf16-pair split
    gather_l1_kernel<<<((NPn + NAn) * 32) / 256, 256>>>();

    // K4: L2 GEMMs, single BN=128 launch
    //     (zph|S2 combined split-epilogue | zah with zero-padded upper half)
    {
        int e0 = gNP;            // combined hp1 task
        int e1 = e0 + gNA;       // zah task
        GTask tc = {p_hp1h, p_hp1l, OFF_W2PC, p_zph, p_S2, p_bc2, NPn, e0, 2};
        GTask tz = {p_ha1h, p_ha1l, OFF_W2AZ, p_zah, nullptr, nullptr, NAn, e1, 3};
        tc_mega<128><<<e1, 256, SMEM128>>>(tc, tz, tz, tz, tz, 0,
                                           nullptr, nullptr, nullptr, nullptr,
                                           nullptr, nullptr);
    }

    // K5: L2 gather -> d_out
    gather_l2_kernel<<<(NPn * 32) / 256, 256>>>(out);
}